// round 6
// baseline (speedup 1.0000x reference)
#include <cuda_runtime.h>
#include <math.h>

#define TOTAL_V 991
#define BATCH   2048
#define NPARTS  20
#define NEPS    9

__device__ __forceinline__ float ex2f_(float x){ float r; asm("ex2.approx.ftz.f32 %0, %1;" : "=f"(r) : "f"(x)); return r; }
__device__ __forceinline__ float lg2f_(float x){ float r; asm("lg2.approx.ftz.f32 %0, %1;" : "=f"(r) : "f"(x)); return r; }

__constant__ float c_eps[NEPS] = {64.f, 16.f, 4.f, 1.f, 0.25f, 0.0625f, 0.015625f, 0.00390625f, 0.0025f};

// Classes: K1 idx0..8 (n 40..45), K2 idx9..11 (n<=35), K3 idx12..15 (61..64),
//          K4 idx16..18 (50..60), K5 idx19 (92). {n, ld, soff, 0}; (ld/4) odd.
__constant__ int4 c_desc[NPARTS] = {
    {45,52,  0,0},{43,44,106,0},{45,52,149,0},{41,44,320,0},{44,44,423,0},
    {44,44,467,0},{42,44,569,0},{40,44,611,0},{41,44,711,0},
    {34,36,286,0},{35,36,752,0},{28,28,851,0},
    {61,68, 45,0},{62,68,361,0},{64,68,787,0},{62,68,929,0},
    {58,60,511,0},{60,60,651,0},{50,52,879,0},
    {92,92,194,0}
};

__device__ float g_scratch[NPARTS * BATCH];

// Fused two-pass partial logsumexp over `lim` float4s; z in registers, scalar math.
template<int N4>
__device__ __forceinline__ void lse_part(const float4* __restrict__ r4,
                                         const float4* __restrict__ v4,
                                         int lim, float nk, float& Mr, float& Sr)
{
    float4 z[N4];
    float M0 = -3.0e38f, M1 = -3.0e38f;
    #pragma unroll
    for (int c = 0; c < N4; c++) if (c < lim) {
        float4 a = r4[c]; float4 w = v4[c];
        z[c].x = fmaf(a.x, nk, w.x);
        z[c].y = fmaf(a.y, nk, w.y);
        z[c].z = fmaf(a.z, nk, w.z);
        z[c].w = fmaf(a.w, nk, w.w);
        M0 = fmaxf(M0, fmaxf(z[c].x, z[c].y));
        M1 = fmaxf(M1, fmaxf(z[c].z, z[c].w));
    }
    const float M = fmaxf(M0, M1);
    float S0 = 0.f, S1 = 0.f, S2 = 0.f, S3 = 0.f;
    #pragma unroll
    for (int c = 0; c < N4; c++) if (c < lim) {
        S0 += ex2f_(z[c].x - M);
        S1 += ex2f_(z[c].y - M);
        S2 += ex2f_(z[c].z - M);
        S3 += ex2f_(z[c].w - M);
    }
    Mr = M; Sr = (S0 + S1) + (S2 + S3);
}

// Warp layout: lanes 0-15 = rows r..r+15 half 0, lanes 16-31 = same rows half 1.
// Group g (sweep f,g,px,py) owns WPG warps; each warp covers 16 rows of both halves.
// Half combine = shfl_xor(16): no shared scratch, no extra barrier.
// Matrices g0:Cxy g1:Cyx g2:Cxx g3:Cyy. Pads: C=+1e30, vec=-1e30 (fmax loses, ex2 FTZ->0).
template<int WPG, int N4, int THREADS, int MINCTAS>
__global__ void __launch_bounds__(THREADS, MINCTAS)
sinkhorn_kernel(const float* __restrict__ pred, const float* __restrict__ pc, int first)
{
    const int pl = blockIdx.x >> 11;
    const int4 d = c_desc[first + pl];
    const int n = d.x, ld = d.y, soff = d.z;
    const int b = blockIdx.x & 2047;
    const int nc4 = ld >> 2;
    const int hc0 = (nc4 + 1) >> 1;    // float4s owned by half 0

    extern __shared__ float sm[];
    const int msz = n * ld;
    float* V  = sm + 4 * msz;          // 8 scaled (double-buffered) + 8 geometry
    float* xx = V + 8*ld;  float* xy = V + 9*ld;   float* xz = V + 10*ld;
    float* yx = V + 11*ld; float* yy = V + 12*ld;  float* yz = V + 13*ld;
    float* x2 = V + 14*ld; float* y2 = V + 15*ld;

    const int t = threadIdx.x;
    const int w = t >> 5, l = t & 31;
    const int g = w / WPG;                       // 0..3
    const int r = (w % WPG) * 16 + (l & 15);
    const int h = l >> 4;
    const bool act = (r < n);

    if (g == 0 && h == 0 && act) {
        const float* X = pred + ((size_t)b * TOTAL_V + soff + r) * 3;
        float ax = X[0], ay = X[1], az = X[2];
        xx[r] = ax; xy[r] = ay; xz[r] = az;
        x2[r] = ax*ax + ay*ay + az*az;
    }
    if (g == 1 && h == 0 && act) {
        const float* Y = pc + ((size_t)b * TOTAL_V + soff + r) * 3;
        float bx = Y[0], by = Y[1], bz = Y[2];
        yx[r] = bx; yy[r] = by; yz[r] = bz;
        y2[r] = bx*bx + by*by + bz*bz;
    }
    for (int j = n + t; j < ld; j += THREADS) {
        #pragma unroll
        for (int a = 0; a < 8; a++) V[a*ld + j] = -1e30f;
    }
    __syncthreads();

    // Build: thread (g,r,h) builds its half of row r of matrix g.
    const int cbase = h ? hc0 : 0;
    const int lim   = h ? (nc4 - hc0) : hc0;
    if (act) {
        const bool lX = (g == 0) || (g == 2);
        const bool rX = (g == 1) || (g == 2);
        const float lx = lX ? xx[r] : yx[r];
        const float ly = lX ? xy[r] : yy[r];
        const float lz = lX ? xz[r] : yz[r];
        const float hl2 = 0.5f * (lX ? x2[r] : y2[r]);
        const float4* ax4 = (const float4*)(rX ? xx : yx) + cbase;
        const float4* ay4 = (const float4*)(rX ? xy : yy) + cbase;
        const float4* az4 = (const float4*)(rX ? xz : yz) + cbase;
        const float4* a24 = (const float4*)(rX ? x2 : y2) + cbase;
        float4* row4 = (float4*)(sm + g*msz + r*ld) + cbase;
        #pragma unroll
        for (int c = 0; c < N4; c++) if (c < lim) {
            float4 ax = ax4[c], ay = ay4[c], az = az4[c], a2 = a24[c];
            float4 o;
            o.x = fmaf(-lx, ax.x, fmaf(-ly, ay.x, fmaf(-lz, az.x, fmaf(0.5f, a2.x, hl2))));
            o.y = fmaf(-lx, ax.y, fmaf(-ly, ay.y, fmaf(-lz, az.y, fmaf(0.5f, a2.y, hl2))));
            o.z = fmaf(-lx, ax.z, fmaf(-ly, ay.z, fmaf(-lz, az.z, fmaf(0.5f, a2.z, hl2))));
            o.w = fmaf(-lx, ax.w, fmaf(-ly, ay.w, fmaf(-lz, az.w, fmaf(0.5f, a2.w, hl2))));
            row4[c] = o;
        }
        if (h == 1) {                    // tail lies in half 1's range
            float* row = sm + g*msz + r*ld;
            for (int j = n; j < ld; j++) row[j] = 1e30f;
        }
    }

    const float LOG2E = 1.44269504088896340736f;
    const float LN2   = 0.69314718055994530942f;
    const float l2n   = lg2f_((float)n);
    const int rg = (g < 2) ? (1 - g) : g;             // vec each group reads
    const float4* rr = (const float4*)(sm + g*msz + r*ld) + cbase;

    float myv = 0.f;

    for (int e = 0; e < NEPS; e++) {
        const float eps = c_eps[e];
        const float k   = LOG2E / eps;
        const float nk  = -k;
        const float c1  = -eps * LN2;
        const float c2  = eps * LN2 * l2n;            // -eps*logb (loga == logb)

        if (act && h == 0) (V + ((e & 1) * 4 + g) * ld)[r] = myv * k;
        __syncthreads();   // single barrier per eps (double-buffered vecs)

        float Mm = -3.0e38f, Sm = 0.f;
        if (act) {
            const float4* vv = (const float4*)(V + ((e & 1) * 4 + rg) * ld) + cbase;
            lse_part<N4>(rr, vv, lim, nk, Mm, Sm);
        }
        // combine halves: executed by ALL lanes (shfl needs full warp)
        const float Mo = __shfl_xor_sync(0xffffffffu, Mm, 16);
        const float So = __shfl_xor_sync(0xffffffffu, Sm, 16);
        if (act) {
            const float M = fmaxf(Mm, Mo);
            const float S = fmaf(Sm, ex2f_(Mm - M), So * ex2f_(Mo - M));
            myv = 0.5f * (myv + fmaf(c1, M + lg2f_(S), c2));
        }
    }
    __syncthreads();   // protect V reuse as reduction scratch

    // div = (sum_f + sum_g - sum_px - sum_py)/n ; one contribution per (g,r): h==0
    float val = (act && h == 0) ? ((g < 2) ? myv : -myv) : 0.f;
    #pragma unroll
    for (int o = 16; o; o >>= 1) val += __shfl_xor_sync(0xffffffffu, val, o);
    if ((t & 31) == 0) V[t >> 5] = val;
    __syncthreads();
    if (t == 0) {
        float s = 0.f;
        const int nw = THREADS / 32;
        for (int ww = 0; ww < nw; ww++) s += V[ww];
        g_scratch[(first + pl) * BATCH + b] = s / (float)n;
    }
}

__global__ void reduce_kernel(float* __restrict__ out)
{
    __shared__ float red[32];
    float s = 0.f;
    for (int i = threadIdx.x; i < NPARTS * BATCH; i += 1024) s += g_scratch[i];
    #pragma unroll
    for (int o = 16; o; o >>= 1) s += __shfl_xor_sync(0xffffffffu, s, o);
    if ((threadIdx.x & 31) == 0) red[threadIdx.x >> 5] = s;
    __syncthreads();
    if (threadIdx.x < 32) {
        float v = red[threadIdx.x];
        #pragma unroll
        for (int o = 16; o; o >>= 1) v += __shfl_xor_sync(0xffffffffu, v, o);
        if (threadIdx.x == 0) out[0] = v * (1.0f / (float)BATCH);
    }
}

extern "C" void kernel_launch(void* const* d_in, const int* in_sizes, int n_in,
                              void* d_out, int out_size)
{
    const float* pred = (const float*)d_in[0];
    const float* pc   = (const float*)d_in[1];

    // smem = (4n + 16) * ld * 4 bytes (max per class)
    const int smem1 = (4*45 + 16) * 52 * 4;   // 40,768  -> 3 CTAs (36 warps)
    const int smem2 = (4*35 + 16) * 36 * 4;   // 22,464  -> 3 CTAs (36 warps)
    const int smem3 = (4*64 + 16) * 68 * 4;   // 73,984  -> 2 CTAs (32 warps)
    const int smem4 = (4*60 + 16) * 60 * 4;   // 61,440  -> 2 CTAs (32 warps)
    const int smem5 = (4*92 + 16) * 92 * 4;   // 141,312 -> 1 CTA  (24 warps)

    // <WPG, N4, THREADS, MINCTAS>: WPG*16 >= n_max; N4 = max ceil(nc4/2)
    cudaFuncSetAttribute((const void*)sinkhorn_kernel<3, 7,384,3>, cudaFuncAttributeMaxDynamicSharedMemorySize, smem1);
    cudaFuncSetAttribute((const void*)sinkhorn_kernel<3, 5,384,3>, cudaFuncAttributeMaxDynamicSharedMemorySize, smem2);
    cudaFuncSetAttribute((const void*)sinkhorn_kernel<4, 9,512,2>, cudaFuncAttributeMaxDynamicSharedMemorySize, smem3);
    cudaFuncSetAttribute((const void*)sinkhorn_kernel<4, 8,512,2>, cudaFuncAttributeMaxDynamicSharedMemorySize, smem4);
    cudaFuncSetAttribute((const void*)sinkhorn_kernel<6,12,768,1>, cudaFuncAttributeMaxDynamicSharedMemorySize, smem5);

    sinkhorn_kernel<3, 7,384,3><<<9 * BATCH, 384, smem1>>>(pred, pc,  0);
    sinkhorn_kernel<3, 5,384,3><<<3 * BATCH, 384, smem2>>>(pred, pc,  9);
    sinkhorn_kernel<4, 9,512,2><<<4 * BATCH, 512, smem3>>>(pred, pc, 12);
    sinkhorn_kernel<4, 8,512,2><<<3 * BATCH, 512, smem4>>>(pred, pc, 16);
    sinkhorn_kernel<6,12,768,1><<<1 * BATCH, 768, smem5>>>(pred, pc, 19);
    reduce_kernel<<<1, 1024>>>((float*)d_out);
}

// round 7
// speedup vs baseline: 1.2023x; 1.2023x over previous
#include <cuda_runtime.h>
#include <math.h>

#define TOTAL_V 991
#define BATCH   2048
#define NPARTS  20
#define NEPS    9

__device__ __forceinline__ float ex2f_(float x){ float r; asm("ex2.approx.ftz.f32 %0, %1;" : "=f"(r) : "f"(x)); return r; }
__device__ __forceinline__ float lg2f_(float x){ float r; asm("lg2.approx.ftz.f32 %0, %1;" : "=f"(r) : "f"(x)); return r; }

__constant__ float c_eps[NEPS] = {64.f, 16.f, 4.f, 1.f, 0.25f, 0.0625f, 0.015625f, 0.00390625f, 0.0025f};

// Classes: K1 idx0..8 (n 40..45), K2 idx9..11 (n<=35), K3 idx12..15 (61..64),
//          K4 idx16..18 (50..60), K5 idx19 (92). {n, ld, soff, 0}; (ld/4) odd.
__constant__ int4 c_desc[NPARTS] = {
    {45,52,  0,0},{43,44,106,0},{45,52,149,0},{41,44,320,0},{44,44,423,0},
    {44,44,467,0},{42,44,569,0},{40,44,611,0},{41,44,711,0},
    {34,36,286,0},{35,36,752,0},{28,28,851,0},
    {61,68, 45,0},{62,68,361,0},{64,68,787,0},{62,68,929,0},
    {58,60,511,0},{60,60,651,0},{50,52,879,0},
    {92,92,194,0}
};

// regions: 0 = (f+g) sums, 1 = -px sums, 2 = -py sums
__device__ float g_scratch[3 * NPARTS * BATCH];

// Fused two-pass logsumexp over one padded row; z in registers, scalar math.
// Pads: C=+1e30, vec=-1e30 -> z_pad huge-negative finite; fmax loses, ex2 FTZ->0.
template<int N4>
__device__ __forceinline__ float lse_row(const float4* __restrict__ r4,
                                         const float4* __restrict__ v4,
                                         int nc4, float nk, float c1, float c2)
{
    float4 z[N4];
    float M0 = -3.0e38f, M1 = -3.0e38f;
    #pragma unroll
    for (int c = 0; c < N4; c++) if (c < nc4) {
        float4 a = r4[c]; float4 w = v4[c];
        z[c].x = fmaf(a.x, nk, w.x);
        z[c].y = fmaf(a.y, nk, w.y);
        z[c].z = fmaf(a.z, nk, w.z);
        z[c].w = fmaf(a.w, nk, w.w);
        M0 = fmaxf(M0, fmaxf(z[c].x, z[c].y));
        M1 = fmaxf(M1, fmaxf(z[c].z, z[c].w));
    }
    const float M = fmaxf(M0, M1);
    float S0 = 0.f, S1 = 0.f, S2 = 0.f, S3 = 0.f;
    #pragma unroll
    for (int c = 0; c < N4; c++) if (c < nc4) {
        S0 += ex2f_(z[c].x - M);
        S1 += ex2f_(z[c].y - M);
        S2 += ex2f_(z[c].z - M);
        S3 += ex2f_(z[c].w - M);
    }
    return fmaf(c1, M + lg2f_((S0 + S1) + (S2 + S3)), c2);
}

// f/g coupled sweeps: 2 groups (g0 sweeps Cxy rows vs gs, g1 sweeps Cyx rows vs fs).
// smem = (2n + 12) * ld floats. One barrier per eps (double-buffered scaled vecs).
template<int RS, int N4, int THREADS, int MINCTAS>
__global__ void __launch_bounds__(THREADS, MINCTAS)
xy_kernel(const float* __restrict__ pred, const float* __restrict__ pc, int first)
{
    const int pl = blockIdx.x >> 11;
    const int4 d = c_desc[first + pl];
    const int n = d.x, ld = d.y, soff = d.z;
    const int b = blockIdx.x & 2047;
    const int nc4 = ld >> 2;

    extern __shared__ float sm[];
    const int msz = n * ld;
    float* V  = sm + 2 * msz;       // [buf0: fs,gs][buf1: fs,gs] then 8 geometry arrays
    float* xx = V + 4*ld;  float* xy = V + 5*ld;   float* xz = V + 6*ld;  float* x2 = V + 7*ld;
    float* yx = V + 8*ld;  float* yy = V + 9*ld;   float* yz = V + 10*ld; float* y2 = V + 11*ld;

    const int t = threadIdx.x;
    const int g = t / RS;           // 0: f-sweep (Cxy), 1: g-sweep (Cyx), >=2 idle
    const int r = t - g * RS;
    const bool act = (g < 2) && (r < n);

    if (act && g == 0) {
        const float* X = pred + ((size_t)b * TOTAL_V + soff + r) * 3;
        float ax = X[0], ay = X[1], az = X[2];
        xx[r] = ax; xy[r] = ay; xz[r] = az;
        x2[r] = ax*ax + ay*ay + az*az;
    }
    if (act && g == 1) {
        const float* Y = pc + ((size_t)b * TOTAL_V + soff + r) * 3;
        float bx = Y[0], by = Y[1], bz = Y[2];
        yx[r] = bx; yy[r] = by; yz[r] = bz;
        y2[r] = bx*bx + by*by + bz*bz;
    }
    for (int j = n + t; j < ld; j += THREADS) {
        #pragma unroll
        for (int a = 0; a < 4; a++) V[a*ld + j] = -1e30f;
    }
    __syncthreads();

    // Build: g0 builds Cxy row r (left X_r, right Y); g1 builds Cyx row r (left Y_r, right X).
    if (act) {
        const bool lX = (g == 0);
        const float lx = lX ? xx[r] : yx[r];
        const float ly = lX ? xy[r] : yy[r];
        const float lz = lX ? xz[r] : yz[r];
        const float hl2 = 0.5f * (lX ? x2[r] : y2[r]);
        const float4* ax4 = (const float4*)(lX ? yx : xx);
        const float4* ay4 = (const float4*)(lX ? yy : xy);
        const float4* az4 = (const float4*)(lX ? yz : xz);
        const float4* a24 = (const float4*)(lX ? y2 : x2);
        float4* row4 = (float4*)(sm + g*msz + r*ld);
        #pragma unroll
        for (int c = 0; c < N4; c++) if (c < nc4) {
            float4 ax = ax4[c], ay = ay4[c], az = az4[c], a2 = a24[c];
            float4 o;
            o.x = fmaf(-lx, ax.x, fmaf(-ly, ay.x, fmaf(-lz, az.x, fmaf(0.5f, a2.x, hl2))));
            o.y = fmaf(-lx, ax.y, fmaf(-ly, ay.y, fmaf(-lz, az.y, fmaf(0.5f, a2.y, hl2))));
            o.z = fmaf(-lx, ax.z, fmaf(-ly, ay.z, fmaf(-lz, az.z, fmaf(0.5f, a2.z, hl2))));
            o.w = fmaf(-lx, ax.w, fmaf(-ly, ay.w, fmaf(-lz, az.w, fmaf(0.5f, a2.w, hl2))));
            row4[c] = o;
        }
        float* row = sm + g*msz + r*ld;
        for (int j = n; j < ld; j++) row[j] = 1e30f;
    }

    const float LOG2E = 1.44269504088896340736f;
    const float LN2   = 0.69314718055994530942f;
    const float l2n   = lg2f_((float)n);
    const float4* rr = (const float4*)(sm + g*msz + (size_t)r*ld);

    float myv = 0.f;

    for (int e = 0; e < NEPS; e++) {
        const float eps = c_eps[e];
        const float k   = LOG2E / eps;
        const float nk  = -k;
        const float c1  = -eps * LN2;
        const float c2  = eps * LN2 * l2n;     // -eps*logb (loga == logb == -ln n)

        if (act) (V + (e & 1) * 2 * ld + g * ld)[r] = myv * k;   // g0->fs, g1->gs
        __syncthreads();

        if (act) {
            const float4* vv = (const float4*)(V + (e & 1) * 2 * ld + (1 - g) * ld);
            myv = 0.5f * (myv + lse_row<N4>(rr, vv, nc4, nk, c1, c2));
        }
    }
    __syncthreads();

    float val = act ? myv : 0.f;               // Σ(f + g)
    #pragma unroll
    for (int o = 16; o; o >>= 1) val += __shfl_xor_sync(0xffffffffu, val, o);
    if ((t & 31) == 0) V[t >> 5] = val;
    __syncthreads();
    if (t == 0) {
        float s = 0.f;
        #pragma unroll
        for (int w = 0; w < THREADS / 32; w++) s += V[w];
        g_scratch[(0 * NPARTS + first + pl) * BATCH + b] = s / (float)n;
    }
}

// Self sweep (px on X or py on Y): 1 symmetric matrix, 1 group.
// smem = (n + 6) * ld floats. grid = P*4096: part-major, then which(x/y), then batch.
template<int N4, int THREADS, int MINCTAS>
__global__ void __launch_bounds__(THREADS, MINCTAS)
self_kernel(const float* __restrict__ pred, const float* __restrict__ pc, int first)
{
    const unsigned u = blockIdx.x;
    const int pl = u >> 12;
    const int which = (u >> 11) & 1;           // 0: px on pred, 1: py on pc
    const int b = u & 2047;
    const int4 d = c_desc[first + pl];
    const int n = d.x, ld = d.y, soff = d.z;
    const int nc4 = ld >> 2;
    const float* pts = which ? pc : pred;

    extern __shared__ float sm[];
    const int msz = n * ld;
    float* V  = sm + msz;                      // ps buf0, ps buf1, then vx,vy,vz,v2
    float* vx = V + 2*ld; float* vy = V + 3*ld; float* vz = V + 4*ld; float* v2 = V + 5*ld;

    const int r = threadIdx.x;
    const bool act = (r < n);

    if (act) {
        const float* P = pts + ((size_t)b * TOTAL_V + soff + r) * 3;
        float ax = P[0], ay = P[1], az = P[2];
        vx[r] = ax; vy[r] = ay; vz[r] = az;
        v2[r] = ax*ax + ay*ay + az*az;
    }
    for (int j = n + r; j < ld; j += THREADS) { V[j] = -1e30f; V[ld + j] = -1e30f; }
    __syncthreads();

    if (act) {
        const float lx = vx[r], ly = vy[r], lz = vz[r];
        const float hl2 = 0.5f * v2[r];
        const float4* ax4 = (const float4*)vx;
        const float4* ay4 = (const float4*)vy;
        const float4* az4 = (const float4*)vz;
        const float4* a24 = (const float4*)v2;
        float4* row4 = (float4*)(sm + (size_t)r*ld);
        #pragma unroll
        for (int c = 0; c < N4; c++) if (c < nc4) {
            float4 ax = ax4[c], ay = ay4[c], az = az4[c], a2 = a24[c];
            float4 o;
            o.x = fmaf(-lx, ax.x, fmaf(-ly, ay.x, fmaf(-lz, az.x, fmaf(0.5f, a2.x, hl2))));
            o.y = fmaf(-lx, ax.y, fmaf(-ly, ay.y, fmaf(-lz, az.y, fmaf(0.5f, a2.y, hl2))));
            o.z = fmaf(-lx, ax.z, fmaf(-ly, ay.z, fmaf(-lz, az.z, fmaf(0.5f, a2.z, hl2))));
            o.w = fmaf(-lx, ax.w, fmaf(-ly, ay.w, fmaf(-lz, az.w, fmaf(0.5f, a2.w, hl2))));
            row4[c] = o;
        }
        float* row = sm + r*ld;
        for (int j = n; j < ld; j++) row[j] = 1e30f;
    }

    const float LOG2E = 1.44269504088896340736f;
    const float LN2   = 0.69314718055994530942f;
    const float l2n   = lg2f_((float)n);
    const float4* rr = (const float4*)(sm + (size_t)r*ld);

    float myv = 0.f;

    for (int e = 0; e < NEPS; e++) {
        const float eps = c_eps[e];
        const float k   = LOG2E / eps;
        const float nk  = -k;
        const float c1  = -eps * LN2;
        const float c2  = eps * LN2 * l2n;     // -eps*loga

        if (act) (V + (e & 1) * ld)[r] = myv * k;
        __syncthreads();

        if (act) {
            const float4* vv = (const float4*)(V + (e & 1) * ld);
            myv = 0.5f * (myv + lse_row<N4>(rr, vv, nc4, nk, c1, c2));
        }
    }
    __syncthreads();

    float val = act ? myv : 0.f;
    #pragma unroll
    for (int o = 16; o; o >>= 1) val += __shfl_xor_sync(0xffffffffu, val, o);
    if ((r & 31) == 0) V[r >> 5] = val;
    __syncthreads();
    if (r == 0) {
        float s = 0.f;
        #pragma unroll
        for (int w = 0; w < THREADS / 32; w++) s += V[w];
        g_scratch[((1 + which) * NPARTS + first + pl) * BATCH + b] = -s / (float)n;
    }
}

__global__ void reduce_kernel(float* __restrict__ out)
{
    __shared__ float red[32];
    float s = 0.f;
    for (int i = threadIdx.x; i < 3 * NPARTS * BATCH; i += 1024) s += g_scratch[i];
    #pragma unroll
    for (int o = 16; o; o >>= 1) s += __shfl_xor_sync(0xffffffffu, s, o);
    if ((threadIdx.x & 31) == 0) red[threadIdx.x >> 5] = s;
    __syncthreads();
    if (threadIdx.x < 32) {
        float v = red[threadIdx.x];
        #pragma unroll
        for (int o = 16; o; o >>= 1) v += __shfl_xor_sync(0xffffffffu, v, o);
        if (threadIdx.x == 0) out[0] = v * (1.0f / (float)BATCH);
    }
}

extern "C" void kernel_launch(void* const* d_in, const int* in_sizes, int n_in,
                              void* d_out, int out_size)
{
    const float* pred = (const float*)d_in[0];
    const float* pc   = (const float*)d_in[1];

    // xy smem = (2n + 12) * ld_max * 4 ; self smem = (n + 6) * ld_max * 4
    const int sxy1 = (2*45 + 12) * 52 * 4;   // 21,216
    const int sxy2 = (2*35 + 12) * 36 * 4;   // 11,808
    const int sxy3 = (2*64 + 12) * 68 * 4;   // 38,080
    const int sxy4 = (2*60 + 12) * 60 * 4;   // 31,680
    const int sxy5 = (2*92 + 12) * 92 * 4;   // 72,128
    const int ssf1 = (45 + 6) * 52 * 4;      // 10,608
    const int ssf2 = (35 + 6) * 36 * 4;      //  5,904
    const int ssf3 = (64 + 6) * 68 * 4;      // 19,040
    const int ssf4 = (60 + 6) * 60 * 4;      // 15,840
    const int ssf5 = (92 + 6) * 92 * 4;      // 36,064

    cudaFuncSetAttribute((const void*)xy_kernel<45,13, 96,6>, cudaFuncAttributeMaxDynamicSharedMemorySize, sxy1);
    cudaFuncSetAttribute((const void*)xy_kernel<35, 9, 96,6>, cudaFuncAttributeMaxDynamicSharedMemorySize, sxy2);
    cudaFuncSetAttribute((const void*)xy_kernel<64,17,128,4>, cudaFuncAttributeMaxDynamicSharedMemorySize, sxy3);
    cudaFuncSetAttribute((const void*)xy_kernel<60,15,128,4>, cudaFuncAttributeMaxDynamicSharedMemorySize, sxy4);
    cudaFuncSetAttribute((const void*)xy_kernel<92,23,192,2>, cudaFuncAttributeMaxDynamicSharedMemorySize, sxy5);
    cudaFuncSetAttribute((const void*)self_kernel<13, 64,10>, cudaFuncAttributeMaxDynamicSharedMemorySize, ssf1);
    cudaFuncSetAttribute((const void*)self_kernel< 9, 64,12>, cudaFuncAttributeMaxDynamicSharedMemorySize, ssf2);
    cudaFuncSetAttribute((const void*)self_kernel<17, 64, 8>, cudaFuncAttributeMaxDynamicSharedMemorySize, ssf3);
    cudaFuncSetAttribute((const void*)self_kernel<15, 64, 9>, cudaFuncAttributeMaxDynamicSharedMemorySize, ssf4);
    cudaFuncSetAttribute((const void*)self_kernel<23, 96, 5>, cudaFuncAttributeMaxDynamicSharedMemorySize, ssf5);

    // xy: grid = P * 2048 ; self: grid = P * 4096 (x and y halves fused)
    xy_kernel<45,13, 96,6><<<9 * BATCH, 96, sxy1>>>(pred, pc,  0);
    self_kernel<13, 64,10><<<9 * 2 * BATCH, 64, ssf1>>>(pred, pc,  0);
    xy_kernel<35, 9, 96,6><<<3 * BATCH, 96, sxy2>>>(pred, pc,  9);
    self_kernel< 9, 64,12><<<3 * 2 * BATCH, 64, ssf2>>>(pred, pc,  9);
    xy_kernel<64,17,128,4><<<4 * BATCH, 128, sxy3>>>(pred, pc, 12);
    self_kernel<17, 64, 8><<<4 * 2 * BATCH, 64, ssf3>>>(pred, pc, 12);
    xy_kernel<60,15,128,4><<<3 * BATCH, 128, sxy4>>>(pred, pc, 16);
    self_kernel<15, 64, 9><<<3 * 2 * BATCH, 64, ssf4>>>(pred, pc, 16);
    xy_kernel<92,23,192,2><<<1 * BATCH, 192, sxy5>>>(pred, pc, 19);
    self_kernel<23, 96, 5><<<1 * 2 * BATCH, 96, ssf5>>>(pred, pc, 19);
    reduce_kernel<<<1, 1024>>>((float*)d_out);
}

// round 8
// speedup vs baseline: 1.2281x; 1.0215x over previous
#include <cuda_runtime.h>
#include <math.h>

#define TOTAL_V 991
#define BATCH   2048
#define NPARTS  20
#define NEPS    9

__device__ __forceinline__ float ex2f_(float x){ float r; asm("ex2.approx.ftz.f32 %0, %1;" : "=f"(r) : "f"(x)); return r; }
__device__ __forceinline__ float lg2f_(float x){ float r; asm("lg2.approx.ftz.f32 %0, %1;" : "=f"(r) : "f"(x)); return r; }

__constant__ float c_eps[NEPS] = {64.f, 16.f, 4.f, 1.f, 0.25f, 0.0625f, 0.015625f, 0.00390625f, 0.0025f};

// {n, ld(storage stride, ld/4 odd), soff, nc4=ceil(n/4) processed}
// idx 0..2 : quadA (n=40,34,35)   idx 3: quadB (n=50)
// idx 4..11: P1 (n 41..45)        idx 12: P2 (n=28)
// idx 13..16: P3 (61..64)         idx 17,18: P4 (58,60)   idx 19: P5 (92)
__constant__ int4 c_desc[NPARTS] = {
    {40,44,611,10},{34,36,286, 9},{35,36,752, 9},
    {50,52,879,13},
    {45,52,  0,12},{45,52,149,12},{43,44,106,11},{41,44,320,11},
    {41,44,711,11},{44,44,423,11},{44,44,467,11},{42,44,569,11},
    {28,28,851, 7},
    {61,68, 45,16},{62,68,361,16},{62,68,929,16},{64,68,787,16},
    {58,60,511,15},{60,60,651,15},
    {92,92,194,23}
};

// region 0: xy/quad sums, region 1: self sums (quad parts leave region1 = 0)
__device__ float g_scratch[2 * NPARTS * BATCH];

// Fused two-pass logsumexp over nc4 float4s; z in registers.
// Pads: C=+1e30, vec=-1e30 -> z_pad huge-negative finite; fmax loses, ex2 FTZ->0.
template<int N4>
__device__ __forceinline__ float lse_row(const float4* __restrict__ r4,
                                         const float4* __restrict__ v4,
                                         int nc4, float nk, float c1, float c2)
{
    float4 z[N4];
    float M0 = -3.0e38f, M1 = -3.0e38f;
    #pragma unroll
    for (int c = 0; c < N4; c++) if (c < nc4) {
        float4 a = r4[c]; float4 w = v4[c];
        z[c].x = fmaf(a.x, nk, w.x);
        z[c].y = fmaf(a.y, nk, w.y);
        z[c].z = fmaf(a.z, nk, w.z);
        z[c].w = fmaf(a.w, nk, w.w);
        M0 = fmaxf(M0, fmaxf(z[c].x, z[c].y));
        M1 = fmaxf(M1, fmaxf(z[c].z, z[c].w));
    }
    const float M = fmaxf(M0, M1);
    float S0 = 0.f, S1 = 0.f, S2 = 0.f, S3 = 0.f;
    #pragma unroll
    for (int c = 0; c < N4; c++) if (c < nc4) {
        S0 += ex2f_(z[c].x - M);
        S1 += ex2f_(z[c].y - M);
        S2 += ex2f_(z[c].z - M);
        S3 += ex2f_(z[c].w - M);
    }
    return fmaf(c1, M + lg2f_((S0 + S1) + (S2 + S3)), c2);
}

__device__ __forceinline__ void build_row(float* __restrict__ rowp, int g, int msz, int r, int ld,
                                          bool lX, bool rX, int n, int nc4,
                                          const float* xx, const float* xy, const float* xz, const float* x2,
                                          const float* yx, const float* yy, const float* yz, const float* y2,
                                          int N4)
{
    const float lx = lX ? xx[r] : yx[r];
    const float ly = lX ? xy[r] : yy[r];
    const float lz = lX ? xz[r] : yz[r];
    const float hl2 = 0.5f * (lX ? x2[r] : y2[r]);
    const float4* ax4 = (const float4*)(rX ? xx : yx);
    const float4* ay4 = (const float4*)(rX ? xy : yy);
    const float4* az4 = (const float4*)(rX ? xz : yz);
    const float4* a24 = (const float4*)(rX ? x2 : y2);
    float4* row4 = (float4*)rowp;
    for (int c = 0; c < nc4; c++) {
        float4 ax = ax4[c], ay = ay4[c], az = az4[c], a2 = a24[c];
        float4 o;
        o.x = fmaf(-lx, ax.x, fmaf(-ly, ay.x, fmaf(-lz, az.x, fmaf(0.5f, a2.x, hl2))));
        o.y = fmaf(-lx, ax.y, fmaf(-ly, ay.y, fmaf(-lz, az.y, fmaf(0.5f, a2.y, hl2))));
        o.z = fmaf(-lx, ax.z, fmaf(-ly, ay.z, fmaf(-lz, az.z, fmaf(0.5f, a2.z, hl2))));
        o.w = fmaf(-lx, ax.w, fmaf(-ly, ay.w, fmaf(-lz, az.w, fmaf(0.5f, a2.w, hl2))));
        row4[c] = o;
    }
    for (int j = n; j < 4 * nc4; j++) rowp[j] = 1e30f;   // overwrite tail garbage
}

// Pair kernel: 2n dense rows. SELF=false: g0 sweeps Cxy vs gs, g1 sweeps Cyx vs fs.
// SELF=true: g0 sweeps Cxx vs own pxs, g1 sweeps Cyy vs own pys. smem=(2n+12)*ld.
template<bool SELF, int N4, int THREADS, int MINCTAS>
__global__ void __launch_bounds__(THREADS, MINCTAS)
pair_kernel(const float* __restrict__ pred, const float* __restrict__ pc, int first)
{
    const int pl = blockIdx.x >> 11;
    const int b  = blockIdx.x & 2047;
    const int4 d = c_desc[first + pl];
    const int n = d.x, ld = d.y, soff = d.z, nc4 = d.w;

    extern __shared__ float sm[];
    const int msz = n * ld;
    float* V  = sm + 2 * msz;          // scaled: buf*2*ld + g*ld ; geometry at +4*ld
    float* xx = V + 4*ld;  float* xy = V + 5*ld;  float* xz = V + 6*ld;  float* x2 = V + 7*ld;
    float* yx = V + 8*ld;  float* yy = V + 9*ld;  float* yz = V + 10*ld; float* y2 = V + 11*ld;

    const int t = threadIdx.x;
    const int g = (t >= n) ? 1 : 0;
    const int r = t - g * n;
    const bool act = (t < 2 * n);

    if (act && g == 0) {
        const float* X = pred + ((size_t)b * TOTAL_V + soff + r) * 3;
        float ax = X[0], ay = X[1], az = X[2];
        xx[r] = ax; xy[r] = ay; xz[r] = az;
        x2[r] = ax*ax + ay*ay + az*az;
    }
    if (act && g == 1) {
        const float* Y = pc + ((size_t)b * TOTAL_V + soff + r) * 3;
        float bx = Y[0], by = Y[1], bz = Y[2];
        yx[r] = bx; yy[r] = by; yz[r] = bz;
        y2[r] = bx*bx + by*by + bz*bz;
    }
    for (int j = n + t; j < ld; j += THREADS) {
        #pragma unroll
        for (int a = 0; a < 4; a++) V[a*ld + j] = -1e30f;
    }
    __syncthreads();

    if (act) {
        const bool lX = (g == 0);
        const bool rX = SELF ? (g == 0) : (g == 1);
        build_row(sm + g*msz + r*ld, g, msz, r, ld, lX, rX, n, nc4,
                  xx, xy, xz, x2, yx, yy, yz, y2, N4);
    }

    const float LOG2E = 1.44269504088896340736f;
    const float LN2   = 0.69314718055994530942f;
    const float l2n   = lg2f_((float)n);
    const int rg = SELF ? g : (1 - g);
    const float4* rr = (const float4*)(sm + g*msz + (size_t)r*ld);

    float myv = 0.f;

    for (int e = 0; e < NEPS; e++) {
        const float eps = c_eps[e];
        const float k   = LOG2E / eps;
        const float nk  = -k;
        const float c1  = -eps * LN2;
        const float c2  = eps * LN2 * l2n;     // -eps*log(1/n) term

        if (act) (V + (e & 1) * 2 * ld + g * ld)[r] = myv * k;
        __syncthreads();

        if (act) {
            const float4* vv = (const float4*)(V + (e & 1) * 2 * ld + rg * ld);
            myv = 0.5f * (myv + lse_row<N4>(rr, vv, nc4, nk, c1, c2));
        }
    }
    __syncthreads();

    float val = act ? (SELF ? -myv : myv) : 0.f;
    #pragma unroll
    for (int o = 16; o; o >>= 1) val += __shfl_xor_sync(0xffffffffu, val, o);
    if ((t & 31) == 0) V[t >> 5] = val;
    __syncthreads();
    if (t == 0) {
        float s = 0.f;
        #pragma unroll
        for (int w = 0; w < THREADS / 32; w++) s += V[w];
        g_scratch[(SELF ? NPARTS : 0) * BATCH + ((first + pl) * BATCH + b)] = s / (float)n;
    }
}

// Quad kernel: 4n dense rows, all four sweeps in one CTA. smem=(4n+16)*ld.
template<int N4, int THREADS, int MINCTAS>
__global__ void __launch_bounds__(THREADS, MINCTAS)
quad_kernel(const float* __restrict__ pred, const float* __restrict__ pc, int first)
{
    const int pl = blockIdx.x >> 11;
    const int b  = blockIdx.x & 2047;
    const int4 d = c_desc[first + pl];
    const int n = d.x, ld = d.y, soff = d.z, nc4 = d.w;

    extern __shared__ float sm[];
    const int msz = n * ld;
    float* V  = sm + 4 * msz;          // scaled: buf*4*ld + g*ld ; geometry at +8*ld
    float* xx = V + 8*ld;  float* xy = V + 9*ld;  float* xz = V + 10*ld; float* x2 = V + 11*ld;
    float* yx = V + 12*ld; float* yy = V + 13*ld; float* yz = V + 14*ld; float* y2 = V + 15*ld;

    const int t = threadIdx.x;
    const int g = t / n;               // runtime divide, once
    const int r = t - g * n;
    const bool act = (g < 4);

    if (act && g == 0) {
        const float* X = pred + ((size_t)b * TOTAL_V + soff + r) * 3;
        float ax = X[0], ay = X[1], az = X[2];
        xx[r] = ax; xy[r] = ay; xz[r] = az;
        x2[r] = ax*ax + ay*ay + az*az;
    }
    if (act && g == 1) {
        const float* Y = pc + ((size_t)b * TOTAL_V + soff + r) * 3;
        float bx = Y[0], by = Y[1], bz = Y[2];
        yx[r] = bx; yy[r] = by; yz[r] = bz;
        y2[r] = bx*bx + by*by + bz*bz;
    }
    for (int j = n + t; j < ld; j += THREADS) {
        #pragma unroll
        for (int a = 0; a < 8; a++) V[a*ld + j] = -1e30f;
    }
    __syncthreads();

    if (act) {
        // g0: Cxy(X,Y) g1: Cyx(Y,X) g2: Cxx(X,X) g3: Cyy(Y,Y)
        const bool lX = (g == 0) || (g == 2);
        const bool rX = (g == 1) || (g == 2);
        build_row(sm + g*msz + r*ld, g, msz, r, ld, lX, rX, n, nc4,
                  xx, xy, xz, x2, yx, yy, yz, y2, N4);
    }

    const float LOG2E = 1.44269504088896340736f;
    const float LN2   = 0.69314718055994530942f;
    const float l2n   = lg2f_((float)n);
    const int rg = (g < 2) ? (1 - g) : g;
    const float4* rr = (const float4*)(sm + g*msz + (size_t)r*ld);

    float myv = 0.f;

    for (int e = 0; e < NEPS; e++) {
        const float eps = c_eps[e];
        const float k   = LOG2E / eps;
        const float nk  = -k;
        const float c1  = -eps * LN2;
        const float c2  = eps * LN2 * l2n;

        if (act) (V + (e & 1) * 4 * ld + g * ld)[r] = myv * k;
        __syncthreads();

        if (act) {
            const float4* vv = (const float4*)(V + (e & 1) * 4 * ld + rg * ld);
            myv = 0.5f * (myv + lse_row<N4>(rr, vv, nc4, nk, c1, c2));
        }
    }
    __syncthreads();

    float val = act ? ((g < 2) ? myv : -myv) : 0.f;
    #pragma unroll
    for (int o = 16; o; o >>= 1) val += __shfl_xor_sync(0xffffffffu, val, o);
    if ((t & 31) == 0) V[t >> 5] = val;
    __syncthreads();
    if (t == 0) {
        float s = 0.f;
        #pragma unroll
        for (int w = 0; w < THREADS / 32; w++) s += V[w];
        g_scratch[(first + pl) * BATCH + b] = s / (float)n;
    }
}

__global__ void reduce_kernel(float* __restrict__ out)
{
    __shared__ float red[32];
    float s = 0.f;
    for (int i = threadIdx.x; i < 2 * NPARTS * BATCH; i += 1024) s += g_scratch[i];
    #pragma unroll
    for (int o = 16; o; o >>= 1) s += __shfl_xor_sync(0xffffffffu, s, o);
    if ((threadIdx.x & 31) == 0) red[threadIdx.x >> 5] = s;
    __syncthreads();
    if (threadIdx.x < 32) {
        float v = red[threadIdx.x];
        #pragma unroll
        for (int o = 16; o; o >>= 1) v += __shfl_xor_sync(0xffffffffu, v, o);
        if (threadIdx.x == 0) out[0] = v * (1.0f / (float)BATCH);
    }
}

extern "C" void kernel_launch(void* const* d_in, const int* in_sizes, int n_in,
                              void* d_out, int out_size)
{
    const float* pred = (const float*)d_in[0];
    const float* pc   = (const float*)d_in[1];

    const int smQA = (4*40 + 16) * 44 * 4;   // 30,976 -> 6 CTAs/SM (30 warps)
    const int smQB = (4*50 + 16) * 52 * 4;   // 44,928 -> 4 CTAs/SM (28 warps)
    const int smP1 = (2*45 + 12) * 52 * 4;   // 21,216 -> 10 CTAs/SM (30 warps)
    const int smP2 = (2*28 + 12) * 28 * 4;   //  7,616 -> 15 CTAs/SM (30 warps)
    const int smP3 = (2*64 + 12) * 68 * 4;   // 38,080 -> 5 CTAs/SM (20 warps)
    const int smP4 = (2*60 + 12) * 60 * 4;   // 31,680 -> 5 CTAs/SM (20 warps)
    const int smP5 = (2*92 + 12) * 92 * 4;   // 72,128 -> 2 CTAs/SM (12 warps)

    cudaFuncSetAttribute((const void*)quad_kernel<10,160,6>,        cudaFuncAttributeMaxDynamicSharedMemorySize, smQA);
    cudaFuncSetAttribute((const void*)quad_kernel<13,224,4>,        cudaFuncAttributeMaxDynamicSharedMemorySize, smQB);
    cudaFuncSetAttribute((const void*)pair_kernel<false,12, 96,10>, cudaFuncAttributeMaxDynamicSharedMemorySize, smP1);
    cudaFuncSetAttribute((const void*)pair_kernel<true ,12, 96,10>, cudaFuncAttributeMaxDynamicSharedMemorySize, smP1);
    cudaFuncSetAttribute((const void*)pair_kernel<false, 7, 64,15>, cudaFuncAttributeMaxDynamicSharedMemorySize, smP2);
    cudaFuncSetAttribute((const void*)pair_kernel<true , 7, 64,15>, cudaFuncAttributeMaxDynamicSharedMemorySize, smP2);
    cudaFuncSetAttribute((const void*)pair_kernel<false,16,128, 5>, cudaFuncAttributeMaxDynamicSharedMemorySize, smP3);
    cudaFuncSetAttribute((const void*)pair_kernel<true ,16,128, 5>, cudaFuncAttributeMaxDynamicSharedMemorySize, smP3);
    cudaFuncSetAttribute((const void*)pair_kernel<false,15,128, 5>, cudaFuncAttributeMaxDynamicSharedMemorySize, smP4);
    cudaFuncSetAttribute((const void*)pair_kernel<true ,15,128, 5>, cudaFuncAttributeMaxDynamicSharedMemorySize, smP4);
    cudaFuncSetAttribute((const void*)pair_kernel<false,23,192, 2>, cudaFuncAttributeMaxDynamicSharedMemorySize, smP5);
    cudaFuncSetAttribute((const void*)pair_kernel<true ,23,192, 2>, cudaFuncAttributeMaxDynamicSharedMemorySize, smP5);

    quad_kernel<10,160,6>      <<<3 * BATCH, 160, smQA>>>(pred, pc,  0);   // n=40,34,35
    quad_kernel<13,224,4>      <<<1 * BATCH, 224, smQB>>>(pred, pc,  3);   // n=50
    pair_kernel<false,12, 96,10><<<8 * BATCH,  96, smP1>>>(pred, pc,  4);  // n=41..45
    pair_kernel<true ,12, 96,10><<<8 * BATCH,  96, smP1>>>(pred, pc,  4);
    pair_kernel<false, 7, 64,15><<<1 * BATCH,  64, smP2>>>(pred, pc, 12);  // n=28
    pair_kernel<true , 7, 64,15><<<1 * BATCH,  64, smP2>>>(pred, pc, 12);
    pair_kernel<false,16,128, 5><<<4 * BATCH, 128, smP3>>>(pred, pc, 13);  // n=61..64
    pair_kernel<true ,16,128, 5><<<4 * BATCH, 128, smP3>>>(pred, pc, 13);
    pair_kernel<false,15,128, 5><<<2 * BATCH, 128, smP4>>>(pred, pc, 17);  // n=58,60
    pair_kernel<true ,15,128, 5><<<2 * BATCH, 128, smP4>>>(pred, pc, 17);
    pair_kernel<false,23,192, 2><<<1 * BATCH, 192, smP5>>>(pred, pc, 19);  // n=92
    pair_kernel<true ,23,192, 2><<<1 * BATCH, 192, smP5>>>(pred, pc, 19);
    reduce_kernel<<<1, 1024>>>((float*)d_out);
}

// round 9
// speedup vs baseline: 1.5642x; 1.2736x over previous
#include <cuda_runtime.h>
#include <math.h>

#define TOTAL_V 991
#define BATCH   2048
#define NPARTS  20
#define NEPS    9

__device__ __forceinline__ float ex2f_(float x){ float r; asm("ex2.approx.ftz.f32 %0, %1;" : "=f"(r) : "f"(x)); return r; }
__device__ __forceinline__ float lg2f_(float x){ float r; asm("lg2.approx.ftz.f32 %0, %1;" : "=f"(r) : "f"(x)); return r; }

__constant__ float c_eps[NEPS] = {64.f, 16.f, 4.f, 1.f, 0.25f, 0.0625f, 0.015625f, 0.00390625f, 0.0025f};

// {n, ld (stride, ld/4 odd), soff, 0}; launches grouped by EXACT nc4=ceil(n/4):
// idx0: quad nc4=10 (n=40) | idx1,2: quad nc4=9 (34,35) | idx3: quad nc4=13 (50)
// idx4..9: pair nc4=11 (41,41,42,43,44,44) | idx10,11: pair nc4=12 (45,45)
// idx12: pair nc4=7 (28) | idx13..16: pair nc4=16 (61,62,62,64)
// idx17,18: pair nc4=15 (58,60) | idx19: pair nc4=23 (92)
__constant__ int4 c_desc[NPARTS] = {
    {40,44,611,0},
    {34,36,286,0},{35,36,752,0},
    {50,52,879,0},
    {41,44,320,0},{41,44,711,0},{42,44,569,0},{43,44,106,0},{44,44,423,0},{44,44,467,0},
    {45,52,  0,0},{45,52,149,0},
    {28,28,851,0},
    {61,68, 45,0},{62,68,361,0},{62,68,929,0},{64,68,787,0},
    {58,60,511,0},{60,60,651,0},
    {92,92,194,0}
};

// region 0: xy/quad sums, region 1: self sums (quad parts leave region1 = 0 forever)
__device__ float g_scratch[2 * NPARTS * BATCH];

// Fully-unrolled fused two-pass logsumexp over exactly NC4 float4s (no guards).
// Pads: C=+1e30, vec=-1e30 -> z_pad huge-negative finite; fmax loses, ex2 FTZ->0.
template<int NC4>
__device__ __forceinline__ float lse_row(const float4* __restrict__ r4,
                                         const float4* __restrict__ v4,
                                         float nk, float c1, float c2)
{
    float4 z[NC4];
    float M0 = -3.0e38f, M1 = -3.0e38f;
    #pragma unroll
    for (int c = 0; c < NC4; c++) {
        float4 a = r4[c]; float4 w = v4[c];
        z[c].x = fmaf(a.x, nk, w.x);
        z[c].y = fmaf(a.y, nk, w.y);
        z[c].z = fmaf(a.z, nk, w.z);
        z[c].w = fmaf(a.w, nk, w.w);
        M0 = fmaxf(M0, fmaxf(z[c].x, z[c].y));
        M1 = fmaxf(M1, fmaxf(z[c].z, z[c].w));
    }
    const float M = fmaxf(M0, M1);
    float S0 = 0.f, S1 = 0.f, S2 = 0.f, S3 = 0.f;
    #pragma unroll
    for (int c = 0; c < NC4; c++) {
        S0 += ex2f_(z[c].x - M);
        S1 += ex2f_(z[c].y - M);
        S2 += ex2f_(z[c].z - M);
        S3 += ex2f_(z[c].w - M);
    }
    return fmaf(c1, M + lg2f_((S0 + S1) + (S2 + S3)), c2);
}

template<int NC4>
__device__ __forceinline__ void build_row(float* __restrict__ rowp,
                                          float lx, float ly, float lz, float hl2,
                                          const float* __restrict__ vx, const float* __restrict__ vy,
                                          const float* __restrict__ vz, const float* __restrict__ v2,
                                          int n)
{
    const float4* ax4 = (const float4*)vx;
    const float4* ay4 = (const float4*)vy;
    const float4* az4 = (const float4*)vz;
    const float4* a24 = (const float4*)v2;
    float4* row4 = (float4*)rowp;
    #pragma unroll
    for (int c = 0; c < NC4; c++) {
        float4 ax = ax4[c], ay = ay4[c], az = az4[c], a2 = a24[c];
        float4 o;
        o.x = fmaf(-lx, ax.x, fmaf(-ly, ay.x, fmaf(-lz, az.x, fmaf(0.5f, a2.x, hl2))));
        o.y = fmaf(-lx, ax.y, fmaf(-ly, ay.y, fmaf(-lz, az.y, fmaf(0.5f, a2.y, hl2))));
        o.z = fmaf(-lx, ax.z, fmaf(-ly, ay.z, fmaf(-lz, az.z, fmaf(0.5f, a2.z, hl2))));
        o.w = fmaf(-lx, ax.w, fmaf(-ly, ay.w, fmaf(-lz, az.w, fmaf(0.5f, a2.w, hl2))));
        row4[c] = o;
    }
    for (int j = n; j < 4 * NC4; j++) rowp[j] = 1e30f;   // overwrite tail garbage
}

// Pair kernel: 2n dense rows; self-bit from blockIdx selects xy (Cxy/Cyx) or self (Cxx/Cyy).
// smem = (2n + 12) * ld floats. One barrier per eps (double-buffered scaled vectors).
template<int NC4, int THREADS, int MINCTAS>
__global__ void __launch_bounds__(THREADS, MINCTAS)
pair_kernel(const float* __restrict__ pred, const float* __restrict__ pc, int first)
{
    const unsigned u = blockIdx.x;
    const int pl   = u >> 12;
    const int self = (u >> 11) & 1;
    const int b    = u & 2047;
    const int4 d = c_desc[first + pl];
    const int n = d.x, ld = d.y, soff = d.z;

    extern __shared__ float sm[];
    const int msz = n * ld;
    float* V  = sm + 2 * msz;          // scaled: buf*2*ld + g*ld ; geometry at +4*ld
    float* xx = V + 4*ld;  float* xy = V + 5*ld;  float* xz = V + 6*ld;  float* x2 = V + 7*ld;
    float* yx = V + 8*ld;  float* yy = V + 9*ld;  float* yz = V + 10*ld; float* y2 = V + 11*ld;

    const int t = threadIdx.x;
    const int g = (t >= n) ? 1 : 0;
    const int r = t - g * n;
    const bool act = (t < 2 * n);

    if (act && g == 0) {
        const float* X = pred + ((size_t)b * TOTAL_V + soff + r) * 3;
        float ax = X[0], ay = X[1], az = X[2];
        xx[r] = ax; xy[r] = ay; xz[r] = az;
        x2[r] = ax*ax + ay*ay + az*az;
    }
    if (act && g == 1) {
        const float* Y = pc + ((size_t)b * TOTAL_V + soff + r) * 3;
        float bx = Y[0], by = Y[1], bz = Y[2];
        yx[r] = bx; yy[r] = by; yz[r] = bz;
        y2[r] = bx*bx + by*by + bz*bz;
    }
    for (int j = n + t; j < ld; j += THREADS) {
        #pragma unroll
        for (int a = 0; a < 4; a++) V[a*ld + j] = -1e30f;
    }
    __syncthreads();

    if (act) {
        // xy: g0 row of Cxy(X_r vs Y), g1 row of Cyx(Y_r vs X). self: g0 Cxx, g1 Cyy.
        const bool lX = (g == 0);
        const bool rX = self ? (g == 0) : (g == 1);
        const float lx = lX ? xx[r] : yx[r];
        const float ly = lX ? xy[r] : yy[r];
        const float lz = lX ? xz[r] : yz[r];
        const float hl2 = 0.5f * (lX ? x2[r] : y2[r]);
        build_row<NC4>(sm + g*msz + r*ld, lx, ly, lz, hl2,
                       rX ? xx : yx, rX ? xy : yy, rX ? xz : yz, rX ? x2 : y2, n);
    }

    const float LOG2E = 1.44269504088896340736f;
    const float LN2   = 0.69314718055994530942f;
    const float l2n   = lg2f_((float)n);
    const int rg = self ? g : (1 - g);
    const float4* rr = (const float4*)(sm + g*msz + (size_t)r*ld);

    float myv = 0.f;

    for (int e = 0; e < NEPS; e++) {
        const float eps = c_eps[e];
        const float k   = LOG2E / eps;
        const float nk  = -k;
        const float c1  = -eps * LN2;
        const float c2  = eps * LN2 * l2n;     // -eps * log(1/n)

        if (act) (V + (e & 1) * 2 * ld + g * ld)[r] = myv * k;
        __syncthreads();

        if (act) {
            const float4* vv = (const float4*)(V + (e & 1) * 2 * ld + rg * ld);
            myv = 0.5f * (myv + lse_row<NC4>(rr, vv, nk, c1, c2));
        }
    }
    __syncthreads();

    float val = act ? (self ? -myv : myv) : 0.f;
    #pragma unroll
    for (int o = 16; o; o >>= 1) val += __shfl_xor_sync(0xffffffffu, val, o);
    if ((t & 31) == 0) V[t >> 5] = val;
    __syncthreads();
    if (t == 0) {
        float s = 0.f;
        #pragma unroll
        for (int w = 0; w < THREADS / 32; w++) s += V[w];
        g_scratch[(self ? NPARTS : 0) * BATCH + ((first + pl) * BATCH + b)] = s / (float)n;
    }
}

// Quad kernel: 4n dense rows, all four sweeps in one CTA. smem=(4n+16)*ld.
template<int NC4, int THREADS, int MINCTAS>
__global__ void __launch_bounds__(THREADS, MINCTAS)
quad_kernel(const float* __restrict__ pred, const float* __restrict__ pc, int first)
{
    const int pl = blockIdx.x >> 11;
    const int b  = blockIdx.x & 2047;
    const int4 d = c_desc[first + pl];
    const int n = d.x, ld = d.y, soff = d.z;

    extern __shared__ float sm[];
    const int msz = n * ld;
    float* V  = sm + 4 * msz;          // scaled: buf*4*ld + g*ld ; geometry at +8*ld
    float* xx = V + 8*ld;  float* xy = V + 9*ld;  float* xz = V + 10*ld; float* x2 = V + 11*ld;
    float* yx = V + 12*ld; float* yy = V + 13*ld; float* yz = V + 14*ld; float* y2 = V + 15*ld;

    const int t = threadIdx.x;
    const int g = t / n;               // one runtime divide
    const int r = t - g * n;
    const bool act = (g < 4);

    if (act && g == 0) {
        const float* X = pred + ((size_t)b * TOTAL_V + soff + r) * 3;
        float ax = X[0], ay = X[1], az = X[2];
        xx[r] = ax; xy[r] = ay; xz[r] = az;
        x2[r] = ax*ax + ay*ay + az*az;
    }
    if (act && g == 1) {
        const float* Y = pc + ((size_t)b * TOTAL_V + soff + r) * 3;
        float bx = Y[0], by = Y[1], bz = Y[2];
        yx[r] = bx; yy[r] = by; yz[r] = bz;
        y2[r] = bx*bx + by*by + bz*bz;
    }
    for (int j = n + t; j < ld; j += THREADS) {
        #pragma unroll
        for (int a = 0; a < 8; a++) V[a*ld + j] = -1e30f;
    }
    __syncthreads();

    if (act) {
        // g0: Cxy(X,Y) g1: Cyx(Y,X) g2: Cxx g3: Cyy
        const bool lX = (g == 0) || (g == 2);
        const bool rX = (g == 1) || (g == 2);
        const float lx = lX ? xx[r] : yx[r];
        const float ly = lX ? xy[r] : yy[r];
        const float lz = lX ? xz[r] : yz[r];
        const float hl2 = 0.5f * (lX ? x2[r] : y2[r]);
        build_row<NC4>(sm + g*msz + r*ld, lx, ly, lz, hl2,
                       rX ? xx : yx, rX ? xy : yy, rX ? xz : yz, rX ? x2 : y2, n);
    }

    const float LOG2E = 1.44269504088896340736f;
    const float LN2   = 0.69314718055994530942f;
    const float l2n   = lg2f_((float)n);
    const int rg = (g < 2) ? (1 - g) : g;
    const float4* rr = (const float4*)(sm + g*msz + (size_t)r*ld);

    float myv = 0.f;

    for (int e = 0; e < NEPS; e++) {
        const float eps = c_eps[e];
        const float k   = LOG2E / eps;
        const float nk  = -k;
        const float c1  = -eps * LN2;
        const float c2  = eps * LN2 * l2n;

        if (act) (V + (e & 1) * 4 * ld + g * ld)[r] = myv * k;
        __syncthreads();

        if (act) {
            const float4* vv = (const float4*)(V + (e & 1) * 4 * ld + rg * ld);
            myv = 0.5f * (myv + lse_row<NC4>(rr, vv, nk, c1, c2));
        }
    }
    __syncthreads();

    float val = act ? ((g < 2) ? myv : -myv) : 0.f;
    #pragma unroll
    for (int o = 16; o; o >>= 1) val += __shfl_xor_sync(0xffffffffu, val, o);
    if ((t & 31) == 0) V[t >> 5] = val;
    __syncthreads();
    if (t == 0) {
        float s = 0.f;
        #pragma unroll
        for (int w = 0; w < THREADS / 32; w++) s += V[w];
        g_scratch[(first + pl) * BATCH + b] = s / (float)n;
    }
}

__global__ void reduce_kernel(float* __restrict__ out)
{
    __shared__ float red[32];
    float s = 0.f;
    for (int i = threadIdx.x; i < 2 * NPARTS * BATCH; i += 1024) s += g_scratch[i];
    #pragma unroll
    for (int o = 16; o; o >>= 1) s += __shfl_xor_sync(0xffffffffu, s, o);
    if ((threadIdx.x & 31) == 0) red[threadIdx.x >> 5] = s;
    __syncthreads();
    if (threadIdx.x < 32) {
        float v = red[threadIdx.x];
        #pragma unroll
        for (int o = 16; o; o >>= 1) v += __shfl_xor_sync(0xffffffffu, v, o);
        if (threadIdx.x == 0) out[0] = v * (1.0f / (float)BATCH);
    }
}

extern "C" void kernel_launch(void* const* d_in, const int* in_sizes, int n_in,
                              void* d_out, int out_size)
{
    const float* pred = (const float*)d_in[0];
    const float* pc   = (const float*)d_in[1];

    const int smQ10 = (4*40 + 16) * 44 * 4;   // 30,976
    const int smQ9  = (4*35 + 16) * 36 * 4;   // 22,464
    const int smQ13 = (4*50 + 16) * 52 * 4;   // 44,928
    const int smP11 = (2*44 + 12) * 44 * 4;   // 17,600
    const int smP12 = (2*45 + 12) * 52 * 4;   // 21,216
    const int smP7  = (2*28 + 12) * 28 * 4;   //  7,616
    const int smP16 = (2*64 + 12) * 68 * 4;   // 38,080
    const int smP15 = (2*60 + 12) * 60 * 4;   // 31,680
    const int smP23 = (2*92 + 12) * 92 * 4;   // 72,128

    cudaFuncSetAttribute((const void*)quad_kernel<10,160,5>, cudaFuncAttributeMaxDynamicSharedMemorySize, smQ10);
    cudaFuncSetAttribute((const void*)quad_kernel< 9,160,6>, cudaFuncAttributeMaxDynamicSharedMemorySize, smQ9);
    cudaFuncSetAttribute((const void*)quad_kernel<13,224,4>, cudaFuncAttributeMaxDynamicSharedMemorySize, smQ13);
    cudaFuncSetAttribute((const void*)pair_kernel<11, 96,10>, cudaFuncAttributeMaxDynamicSharedMemorySize, smP11);
    cudaFuncSetAttribute((const void*)pair_kernel<12, 96,10>, cudaFuncAttributeMaxDynamicSharedMemorySize, smP12);
    cudaFuncSetAttribute((const void*)pair_kernel< 7, 64,15>, cudaFuncAttributeMaxDynamicSharedMemorySize, smP7);
    cudaFuncSetAttribute((const void*)pair_kernel<16,128, 5>, cudaFuncAttributeMaxDynamicSharedMemorySize, smP16);
    cudaFuncSetAttribute((const void*)pair_kernel<15,128, 5>, cudaFuncAttributeMaxDynamicSharedMemorySize, smP15);
    cudaFuncSetAttribute((const void*)pair_kernel<23,192, 2>, cudaFuncAttributeMaxDynamicSharedMemorySize, smP23);

    // quads: grid = P * 2048 ; pairs: grid = P * 4096 (xy and self fused via bit 11)
    quad_kernel<10,160,5><<<1 * BATCH, 160, smQ10>>>(pred, pc,  0);   // n=40
    quad_kernel< 9,160,6><<<2 * BATCH, 160, smQ9 >>>(pred, pc,  1);   // n=34,35
    quad_kernel<13,224,4><<<1 * BATCH, 224, smQ13>>>(pred, pc,  3);   // n=50
    pair_kernel<11, 96,10><<<6 * 2 * BATCH,  96, smP11>>>(pred, pc,  4);  // n=41..44
    pair_kernel<12, 96,10><<<2 * 2 * BATCH,  96, smP12>>>(pred, pc, 10);  // n=45,45
    pair_kernel< 7, 64,15><<<1 * 2 * BATCH,  64, smP7 >>>(pred, pc, 12);  // n=28
    pair_kernel<16,128, 5><<<4 * 2 * BATCH, 128, smP16>>>(pred, pc, 13);  // n=61..64
    pair_kernel<15,128, 5><<<2 * 2 * BATCH, 128, smP15>>>(pred, pc, 17);  // n=58,60
    pair_kernel<23,192, 2><<<1 * 2 * BATCH, 192, smP23>>>(pred, pc, 19);  // n=92
    reduce_kernel<<<1, 1024>>>((float*)d_out);
}